// round 2
// baseline (speedup 1.0000x reference)
#include <cuda_runtime.h>

#define HT 160
#define WDx 160
#define HWPIX 25600
#define NB 2
#define NPIX (NB * HWPIX)
#define CCH 64
#define NSETC 32

typedef unsigned long long ull;

__device__ __forceinline__ ull pack2(float a, float b) {
    ull r; asm("mov.b64 %0, {%1, %2};" : "=l"(r) : "f"(a), "f"(b)); return r;
}
__device__ __forceinline__ ull dup2(float a) {
    ull r; asm("mov.b64 %0, {%1, %1};" : "=l"(r) : "f"(a)); return r;
}
__device__ __forceinline__ ull fma2(ull a, ull b, ull c) {
    ull r; asm("fma.rn.f32x2 %0, %1, %2, %3;" : "=l"(r) : "l"(a), "l"(b), "l"(c)); return r;
}
__device__ __forceinline__ ull add2(ull a, ull b) {
    ull r; asm("add.rn.f32x2 %0, %1, %2;" : "=l"(r) : "l"(a), "l"(b)); return r;
}
__device__ __forceinline__ ull mul2(ull a, ull b) {
    ull r; asm("mul.rn.f32x2 %0, %1, %2;" : "=l"(r) : "l"(a), "l"(b)); return r;
}

// ---------------- scratch (device globals: no allocation allowed) ----------
__device__ float g_x[NPIX * CCH];     // LN1 output, [b][c][hw]
__device__ float g_att[NPIX * NSETC]; // attention maps [b][n][hw]
__device__ float g_u1[NPIX * CCH];    // conv1x1a output
__device__ float g_uf[NPIX * CCH];    // unfolded-feature conv output
__device__ float g_z[NPIX * CCH];     // pre-conv3 combined
__device__ float g_y[NPIX * CCH];     // mid residual
__device__ float g_xmean[NB * CCH];
__device__ float g_sca[NB * CCH];

// ---------------- K1: LayerNorm over channels (per pixel) ------------------
__global__ void ln1_kernel(const float* __restrict__ inp,
                           const float* __restrict__ w,
                           const float* __restrict__ b) {
    int p = blockIdx.x * blockDim.x + threadIdx.x;
    if (p >= NPIX) return;
    int bi = p / HWPIX, hw = p - bi * HWPIX;
    const float* src = inp + (size_t)bi * CCH * HWPIX + hw;
    float v[64];
    float s = 0.f;
#pragma unroll
    for (int c = 0; c < 64; c++) { v[c] = src[c * HWPIX]; s += v[c]; }
    float mu = s * (1.f / 64.f);
    float q = 0.f;
#pragma unroll
    for (int c = 0; c < 64; c++) { float d = v[c] - mu; q += d * d; }
    float rinv = rsqrtf(q * (1.f / 64.f) + 1e-6f);
    float* dst = g_x + (size_t)bi * CCH * HWPIX + hw;
#pragma unroll
    for (int c = 0; c < 64; c++)
        dst[c * HWPIX] = (v[c] - mu) * rinv * w[c] + b[c];
}

// ---------------- K2: per-(b,c) spatial mean of g_x ------------------------
__global__ void mean_kernel() {
    int bc = blockIdx.x; // 0..127
    const float* src = g_x + (size_t)bc * HWPIX;
    float s = 0.f;
    for (int i = threadIdx.x; i < HWPIX; i += blockDim.x) s += src[i];
#pragma unroll
    for (int o = 16; o > 0; o >>= 1) s += __shfl_down_sync(0xffffffffu, s, o);
    __shared__ float red[8];
    if ((threadIdx.x & 31) == 0) red[threadIdx.x >> 5] = s;
    __syncthreads();
    if (threadIdx.x == 0) {
        float t = 0.f;
        for (int i = 0; i < 8; i++) t += red[i];
        g_xmean[bc] = t * (1.f / HWPIX);
    }
}

// ---------------- K3: sca = 1x1 conv on pooled means -----------------------
__global__ void sca_kernel(const float* __restrict__ w, const float* __restrict__ b) {
    int t = threadIdx.x;
    if (t < NB * CCH) {
        int bi = t >> 6, c = t & 63;
        float a = b[c];
#pragma unroll
        for (int k = 0; k < 64; k++) a += w[c * 64 + k] * g_xmean[bi * 64 + k];
        g_sca[t] = a;
    }
}

// ---------------- K4: attention path (grouped3x3 + gate + 1x1) -------------
__global__ void att_kernel(const float* __restrict__ c2a_w, const float* __restrict__ c2a_b,
                           const float* __restrict__ c2b_w, const float* __restrict__ c2b_b,
                           const float* __restrict__ attgamma) {
    __shared__ float wa[32 * 18];  // c2a weights, same layout as source
    __shared__ float ba[32];
    __shared__ float wbT[16 * 32]; // [j][n]
    __shared__ float bb[32], ag[32];
    for (int i = threadIdx.x; i < 576; i += blockDim.x) wa[i] = c2a_w[i];
    if (threadIdx.x < 32) {
        ba[threadIdx.x] = c2a_b[threadIdx.x];
        bb[threadIdx.x] = c2b_b[threadIdx.x];
        ag[threadIdx.x] = attgamma[threadIdx.x];
    }
    for (int i = threadIdx.x; i < 512; i += blockDim.x) {
        int j = i >> 5, n = i & 31;
        wbT[i] = c2b_w[n * 16 + j];
    }
    __syncthreads();
    int p = blockIdx.x * blockDim.x + threadIdx.x;
    if (p >= NPIX) return;
    int bi = p / HWPIX, hw = p - bi * HWPIX;
    int h = hw / WDx, w = hw - h * WDx;
    const float* xb = g_x + (size_t)bi * CCH * HWPIX;
    float att_acc[32];
#pragma unroll
    for (int n = 0; n < 32; n++) att_acc[n] = 0.f;
#pragma unroll 4
    for (int j = 0; j < 16; j++) {
        float t0 = ba[j], t1 = ba[j + 16];
#pragma unroll
        for (int l = 0; l < 2; l++) {
            const float* xp0 = xb + (2 * j + l) * HWPIX;
            const float* xp1 = xb + (2 * (j + 16) + l) * HWPIX;
#pragma unroll
            for (int dy = 0; dy < 3; dy++) {
                int hy = h + dy - 1;
                bool vy = ((unsigned)hy < HT);
#pragma unroll
                for (int dx = 0; dx < 3; dx++) {
                    int wx = w + dx - 1;
                    bool ok = vy && ((unsigned)wx < WDx);
                    int off = hy * WDx + wx;
                    float x0 = ok ? xp0[off] : 0.f;
                    float x1 = ok ? xp1[off] : 0.f;
                    t0 += wa[j * 18 + l * 9 + dy * 3 + dx] * x0;
                    t1 += wa[(j + 16) * 18 + l * 9 + dy * 3 + dx] * x1;
                }
            }
        }
        float gj = t0 * t1;
        const float4* wp = (const float4*)&wbT[j * 32];
#pragma unroll
        for (int n4 = 0; n4 < 8; n4++) {
            float4 wv = wp[n4];
            att_acc[4 * n4 + 0] += wv.x * gj;
            att_acc[4 * n4 + 1] += wv.y * gj;
            att_acc[4 * n4 + 2] += wv.z * gj;
            att_acc[4 * n4 + 3] += wv.w * gj;
        }
    }
    float* dst = g_att + (size_t)bi * NSETC * HWPIX + hw;
#pragma unroll
    for (int n = 0; n < 32; n++)
        dst[n * HWPIX] = (att_acc[n] + bb[n]) * ag[n];
}

// ---------------- K5: 1x1 conv 64->64 (c11a) on g_x -> g_u1 ----------------
__global__ void conv1x1_u1(const float* __restrict__ w, const float* __restrict__ b) {
    __shared__ float ws[4096];
    __shared__ float bs[64];
    for (int i = threadIdx.x; i < 4096; i += blockDim.x) ws[i] = w[i];
    if (threadIdx.x < 64) bs[threadIdx.x] = b[threadIdx.x];
    __syncthreads();
    int p = blockIdx.x * blockDim.x + threadIdx.x;
    if (p >= NPIX) return;
    int bi = p / HWPIX, hw = p - bi * HWPIX;
    const float* src = g_x + (size_t)bi * CCH * HWPIX + hw;
    float xin[64];
#pragma unroll
    for (int i = 0; i < 64; i++) xin[i] = src[i * HWPIX];
    float* dst = g_u1 + (size_t)bi * CCH * HWPIX + hw;
#pragma unroll 4
    for (int o = 0; o < 64; o++) {
        float a = bs[o];
        const float4* wp = (const float4*)&ws[o * 64];
#pragma unroll
        for (int i4 = 0; i4 < 16; i4++) {
            float4 wv = wp[i4];
            a += wv.x * xin[4 * i4] + wv.y * xin[4 * i4 + 1] +
                 wv.z * xin[4 * i4 + 2] + wv.w * xin[4 * i4 + 3];
        }
        dst[o * HWPIX] = a;
    }
}

// ---------------- K6: grouped 5x5 conv (16 groups of 4) g_u1 -> g_uf -------
__global__ void uf_kernel(const float* __restrict__ w5, const float* __restrict__ b5) {
    __shared__ float ws[6400]; // [g][ic][kk][oc]
    __shared__ float bs[64];
    for (int i = threadIdx.x; i < 6400; i += blockDim.x) {
        int oc = i & 3;
        int r = i >> 2;          // g*100 + ic*25 + kk
        int g = r / 100;
        int r2 = r - g * 100;
        int ic = r2 / 25, kk = r2 - ic * 25;
        ws[i] = w5[((g * 4 + oc) * 4 + ic) * 25 + kk];
    }
    if (threadIdx.x < 64) bs[threadIdx.x] = b5[threadIdx.x];
    __syncthreads();
    int p = blockIdx.x * blockDim.x + threadIdx.x;
    if (p >= NPIX) return;
    int bi = p / HWPIX, hw = p - bi * HWPIX;
    int h = hw / WDx, w = hw - h * WDx;
    const float* ub = g_u1 + (size_t)bi * CCH * HWPIX;
    float* dst = g_uf + (size_t)bi * CCH * HWPIX + hw;
    for (int g = 0; g < 16; g++) {
        float a0 = bs[g * 4 + 0], a1 = bs[g * 4 + 1], a2 = bs[g * 4 + 2], a3 = bs[g * 4 + 3];
        const float* gin = ub + (g * 4) * HWPIX;
#pragma unroll
        for (int dy = 0; dy < 5; dy++) {
            int hy = h + dy - 2;
            bool vy = ((unsigned)hy < HT);
#pragma unroll
            for (int dx = 0; dx < 5; dx++) {
                int wx = w + dx - 2;
                bool ok = vy && ((unsigned)wx < WDx);
                int off = hy * WDx + wx;
                int kk = dy * 5 + dx;
#pragma unroll
                for (int ic = 0; ic < 4; ic++) {
                    float v = ok ? gin[ic * HWPIX + off] : 0.f;
                    const float4 wv = *(const float4*)&ws[(g * 100 + ic * 25 + kk) * 4];
                    a0 += wv.x * v; a1 += wv.y * v; a2 += wv.z * v; a3 += wv.w * v;
                }
            }
        }
        dst[(g * 4 + 0) * HWPIX] = a0;
        dst[(g * 4 + 1) * HWPIX] = a1;
        dst[(g * 4 + 2) * HWPIX] = a2;
        dst[(g * 4 + 3) * HWPIX] = a3;
    }
}

// ---------------- K7: fused KBA (two-stage GEMM, f32x2) -> g_z -------------
// Tile: 128 consecutive hw pixels = 64 pixel-pairs per block, 256 threads.
// Stage 1 per group g: s[m=(o*32+n), pair] = sum_{k<37} W[m,k]*patch2[k,pair]
//   (k=36 is the kb_b bias column with patch2=1)
// Stage 2: out[c=(g,o), pair] = sum_n att2[n,pair]*s[o*32+n, pair],
//   then z = (out*ga1[c] + uf_center)*sca, written as float2.
#define KBA_SMEM_BYTES (37*128*4 + 37*64*8 + 32*65*8)
__global__ void kba_kernel(const float* __restrict__ kb_w,
                           const float* __restrict__ kb_b,
                           const float* __restrict__ ga1) {
    extern __shared__ char smem[];
    float* Ws      = (float*)smem;                       // [37][128]  18944 B
    ull*   patch2s = (ull*)(smem + 37 * 128 * 4);        // [37][64]   18944 B
    ull*   att2s   = (ull*)(smem + 37 * 128 * 4 + 37 * 64 * 8); // [32][65] 16640 B

    int tid = threadIdx.x;
    int bi  = blockIdx.x / (HWPIX / 128);
    int hw0 = (blockIdx.x % (HWPIX / 128)) * 128;

    // stage att pairs (persistent for the block)
    for (int idx = tid; idx < 32 * 64; idx += 256) {
        int n = idx >> 6, pp = idx & 63;
        const float2 v = *(const float2*)&g_att[((size_t)bi * 32 + n) * HWPIX + hw0 + 2 * pp];
        att2s[n * 65 + pp] = pack2(v.x, v.y);
    }

    int m_blk = tid & 15;          // 16 m-blocks of 8
    int pp0   = (tid >> 4) * 4;    // 16 pp-blocks of 4 pairs
    int m0    = m_blk * 8;
    int o_out = m_blk >> 2;
    int n0    = (m_blk & 3) * 8;

    for (int g = 0; g < 16; g++) {
        __syncthreads();
        // stage weights: Ws[k][m], m = o*32+n
        for (int idx = tid; idx < 37 * 128; idx += 256) {
            int k = idx >> 7, m = idx & 127;
            int o = m >> 5, n = m & 31;
            float v = (k < 36) ? kb_w[n * 2304 + g * 144 + o * 36 + k]
                               : kb_b[n * 64 + g * 4 + o];
            Ws[idx] = v;
        }
        // stage patches: patch2s[k][pp]
        for (int idx = tid; idx < 36 * 64; idx += 256) {
            int k = idx >> 6, pp = idx & 63;
            int ci = k / 9, kk = k - ci * 9;
            int dy = kk / 3, dx = kk - dy * 3;
            const float* ufc = g_uf + ((size_t)bi * 64 + g * 4 + ci) * HWPIX;
            float v0, v1;
            {
                int p = hw0 + 2 * pp;
                int h = p / WDx, w = p - h * WDx;
                int hy = h + dy - 1, wx = w + dx - 1;
                v0 = ((unsigned)hy < HT && (unsigned)wx < WDx) ? ufc[hy * WDx + wx] : 0.f;
            }
            {
                int p = hw0 + 2 * pp + 1;
                int h = p / WDx, w = p - h * WDx;
                int hy = h + dy - 1, wx = w + dx - 1;
                v1 = ((unsigned)hy < HT && (unsigned)wx < WDx) ? ufc[hy * WDx + wx] : 0.f;
            }
            patch2s[idx] = pack2(v0, v1);
        }
        if (tid < 64) patch2s[36 * 64 + tid] = pack2(1.f, 1.f);
        __syncthreads();

        // ---- stage 1 GEMM: 8m x 4pair register tile per thread ----
        ull acc[8][4];
#pragma unroll
        for (int j = 0; j < 8; j++)
#pragma unroll
            for (int q = 0; q < 4; q++) acc[j][q] = 0ull;

        for (int k = 0; k < 37; k++) {
            ull pv[4];
#pragma unroll
            for (int q = 0; q < 4; q++) pv[q] = patch2s[k * 64 + pp0 + q];
            float4 wA = *(const float4*)&Ws[k * 128 + m0];
            float4 wB = *(const float4*)&Ws[k * 128 + m0 + 4];
            ull w2[8];
            w2[0] = dup2(wA.x); w2[1] = dup2(wA.y); w2[2] = dup2(wA.z); w2[3] = dup2(wA.w);
            w2[4] = dup2(wB.x); w2[5] = dup2(wB.y); w2[6] = dup2(wB.z); w2[7] = dup2(wB.w);
#pragma unroll
            for (int j = 0; j < 8; j++)
#pragma unroll
                for (int q = 0; q < 4; q++)
                    acc[j][q] = fma2(w2[j], pv[q], acc[j][q]);
        }

        // ---- stage 2: contract over n (8 local + 4-lane butterfly) ----
        int c = g * 4 + o_out;
#pragma unroll
        for (int q = 0; q < 4; q++) {
            ull part = 0ull;
#pragma unroll
            for (int j = 0; j < 8; j++)
                part = fma2(att2s[(n0 + j) * 65 + pp0 + q], acc[j][q], part);
            part = add2(part, __shfl_xor_sync(0xffffffffu, part, 1));
            part = add2(part, __shfl_xor_sync(0xffffffffu, part, 2));
            if ((tid & 3) == 0) {
                ull ufc2 = patch2s[(o_out * 9 + 4) * 64 + pp0 + q];
                ull ga2  = dup2(ga1[c]);
                ull sc2  = dup2(g_sca[bi * 64 + c]);
                ull z2 = mul2(fma2(ga2, part, ufc2), sc2);
                float2 zo;
                asm("mov.b64 {%0, %1}, %2;" : "=f"(zo.x), "=f"(zo.y) : "l"(z2));
                *(float2*)&g_z[((size_t)bi * 64 + c) * HWPIX + hw0 + 2 * (pp0 + q)] = zo;
            }
        }
    }
}

// ---------------- K8: conv3 (1x1) + beta residual -> g_y -------------------
__global__ void conv3_res_kernel(const float* __restrict__ inp,
                                 const float* __restrict__ w,
                                 const float* __restrict__ b,
                                 const float* __restrict__ beta) {
    __shared__ float ws[4096];
    __shared__ float bs[64];
    for (int i = threadIdx.x; i < 4096; i += blockDim.x) ws[i] = w[i];
    if (threadIdx.x < 64) bs[threadIdx.x] = b[threadIdx.x];
    __syncthreads();
    int p = blockIdx.x * blockDim.x + threadIdx.x;
    if (p >= NPIX) return;
    int bi = p / HWPIX, hw = p - bi * HWPIX;
    const float* src = g_z + (size_t)bi * CCH * HWPIX + hw;
    const float* rsd = inp + (size_t)bi * CCH * HWPIX + hw;
    float xin[64];
#pragma unroll
    for (int i = 0; i < 64; i++) xin[i] = src[i * HWPIX];
    float* dst = g_y + (size_t)bi * CCH * HWPIX + hw;
#pragma unroll 4
    for (int o = 0; o < 64; o++) {
        float a = bs[o];
        const float4* wp = (const float4*)&ws[o * 64];
#pragma unroll
        for (int i4 = 0; i4 < 16; i4++) {
            float4 wv = wp[i4];
            a += wv.x * xin[4 * i4] + wv.y * xin[4 * i4 + 1] +
                 wv.z * xin[4 * i4 + 2] + wv.w * xin[4 * i4 + 3];
        }
        dst[o * HWPIX] = rsd[o * HWPIX] + a * beta[o];
    }
}

// ---------------- K9: LN2 + FFN (conv4, gate, conv5) + gamma residual ------
__global__ void ffn_kernel(const float* __restrict__ ln2w, const float* __restrict__ ln2b,
                           const float* __restrict__ w4, const float* __restrict__ b4,
                           const float* __restrict__ w5, const float* __restrict__ b5,
                           const float* __restrict__ gamma, float* __restrict__ out) {
    __shared__ float ws[12288]; // [0:8192) w4 [j][i], [8192:12288) w5T [j][o]
    for (int i = threadIdx.x; i < 8192; i += blockDim.x) ws[i] = w4[i];
    for (int i = threadIdx.x; i < 4096; i += blockDim.x) {
        int j = i >> 6, o = i & 63;
        ws[8192 + i] = w5[o * 64 + j];
    }
    __syncthreads();
    int p = blockIdx.x * blockDim.x + threadIdx.x;
    if (p >= NPIX) return;
    int bi = p / HWPIX, hw = p - bi * HWPIX;
    const float* yb = g_y + (size_t)bi * CCH * HWPIX + hw;
    float v[64];
    float s = 0.f;
#pragma unroll
    for (int c = 0; c < 64; c++) { v[c] = yb[c * HWPIX]; s += v[c]; }
    float mu = s * (1.f / 64.f);
    float q = 0.f;
#pragma unroll
    for (int c = 0; c < 64; c++) { float d = v[c] - mu; q += d * d; }
    float rinv = rsqrtf(q * (1.f / 64.f) + 1e-6f);
    float xn[64];
#pragma unroll
    for (int c = 0; c < 64; c++) xn[c] = (v[c] - mu) * rinv * ln2w[c] + ln2b[c];
    float acc[64];
#pragma unroll
    for (int o = 0; o < 64; o++) acc[o] = 0.f;
    for (int j = 0; j < 64; j++) {
        float a = b4[j], bb = b4[j + 64];
        const float4* wpa = (const float4*)&ws[j * 64];
        const float4* wpb = (const float4*)&ws[(j + 64) * 64];
#pragma unroll
        for (int i4 = 0; i4 < 16; i4++) {
            float4 wva = wpa[i4];
            float4 wvb = wpb[i4];
            a  += wva.x * xn[4 * i4] + wva.y * xn[4 * i4 + 1] + wva.z * xn[4 * i4 + 2] + wva.w * xn[4 * i4 + 3];
            bb += wvb.x * xn[4 * i4] + wvb.y * xn[4 * i4 + 1] + wvb.z * xn[4 * i4 + 2] + wvb.w * xn[4 * i4 + 3];
        }
        float gj = a * bb;
        const float4* wp5 = (const float4*)&ws[8192 + j * 64];
#pragma unroll
        for (int o4 = 0; o4 < 16; o4++) {
            float4 wv = wp5[o4];
            acc[4 * o4 + 0] += wv.x * gj;
            acc[4 * o4 + 1] += wv.y * gj;
            acc[4 * o4 + 2] += wv.z * gj;
            acc[4 * o4 + 3] += wv.w * gj;
        }
    }
    float* dst = out + (size_t)bi * CCH * HWPIX + hw;
#pragma unroll
    for (int o = 0; o < 64; o++)
        dst[o * HWPIX] = v[o] + (acc[o] + b5[o]) * gamma[o];
}

// ---------------------------------------------------------------------------
extern "C" void kernel_launch(void* const* d_in, const int* in_sizes, int n_in,
                              void* d_out, int out_size) {
    const float* inp      = (const float*)d_in[0];
    const float* ln1_w    = (const float*)d_in[1];
    const float* ln1_b    = (const float*)d_in[2];
    const float* ln2_w    = (const float*)d_in[3];
    const float* ln2_b    = (const float*)d_in[4];
    const float* sca_w    = (const float*)d_in[5];
    const float* sca_b    = (const float*)d_in[6];
    const float* c11a_w   = (const float*)d_in[7];
    const float* c11a_b   = (const float*)d_in[8];
    const float* c11b_w   = (const float*)d_in[9];
    const float* c11b_b   = (const float*)d_in[10];
    const float* c2a_w    = (const float*)d_in[11];
    const float* c2a_b    = (const float*)d_in[12];
    const float* c2b_w    = (const float*)d_in[13];
    const float* c2b_b    = (const float*)d_in[14];
    const float* conv3_w  = (const float*)d_in[15];
    const float* conv3_b  = (const float*)d_in[16];
    const float* conv4_w  = (const float*)d_in[17];
    const float* conv4_b  = (const float*)d_in[18];
    const float* conv5_w  = (const float*)d_in[19];
    const float* conv5_b  = (const float*)d_in[20];
    const float* kb_w     = (const float*)d_in[21];
    const float* kb_b     = (const float*)d_in[22];
    const float* ga1      = (const float*)d_in[23];
    const float* attgamma = (const float*)d_in[24];
    const float* beta     = (const float*)d_in[25];
    const float* gamma    = (const float*)d_in[26];
    float* out = (float*)d_out;

    cudaFuncSetAttribute(kba_kernel, cudaFuncAttributeMaxDynamicSharedMemorySize,
                         KBA_SMEM_BYTES);

    ln1_kernel<<<NPIX / 256, 256>>>(inp, ln1_w, ln1_b);
    mean_kernel<<<NB * CCH, 256>>>();
    sca_kernel<<<1, 128>>>(sca_w, sca_b);
    att_kernel<<<NPIX / 256, 256>>>(c2a_w, c2a_b, c2b_w, c2b_b, attgamma);
    conv1x1_u1<<<NPIX / 256, 256>>>(c11a_w, c11a_b);
    uf_kernel<<<NPIX / 256, 256>>>(c11b_w, c11b_b);
    kba_kernel<<<NPIX / 128, 256, KBA_SMEM_BYTES>>>(kb_w, kb_b, ga1);
    conv3_res_kernel<<<NPIX / 256, 256>>>(inp, conv3_w, conv3_b, beta);
    ffn_kernel<<<NPIX / 128, 128>>>(ln2_w, ln2_b, conv4_w, conv4_b,
                                    conv5_w, conv5_b, gamma, out);
}